// round 8
// baseline (speedup 1.0000x reference)
#include <cuda_runtime.h>
#include <cuda_bf16.h>

// Problem constants
#define B_   16
#define T_   8
#define E_   2048
#define H_   16
#define HD_  128
#define S_   4096
#define ST_  4104            // S_ + T_
#define BT_  128             // B_*T_
#define NSPLIT 16
#define KPS  256             // keys per split = S_/NSPLIT
#define SPLITK 8
#define SCALE_ 0.08838834764831845f  // hd^-0.5

// Output layout (floats): [out (B,T,E)][k (B,H,ST,HD)][v (B,H,ST,HD)]
#define OFF_K   262144
#define OFF_V   134742016
#define OFF_K4  65536        // OFF_K/4
#define OFF_V4  33685504     // OFF_V/4

// Scratch (static device globals; no allocation allowed)
__device__ float d_q[BT_ * E_];                       // (b,h,t,d), pre-scaled
__device__ float d_part_o[B_*H_*NSPLIT*T_*HD_];       // (blk,t,d)
__device__ float d_part_m[B_*H_*NSPLIT*T_];
__device__ float d_part_l[B_*H_*NSPLIT*T_];
__device__ float d_attn[BT_ * E_];                    // (b,t, h*HD+d)
__device__ float d_p1[SPLITK*128*6144];               // qkv gemm partials
__device__ float d_p2[SPLITK*128*2048];               // out gemm partials

typedef unsigned long long ULL;

__device__ __forceinline__ ULL pack2(float x, float y) {
    ULL r; asm("mov.b64 %0, {%1,%2};" : "=l"(r) : "f"(x), "f"(y)); return r;
}
__device__ __forceinline__ void ffma2(ULL& d, ULL a, ULL b) {
    asm("fma.rn.f32x2 %0, %1, %2, %0;" : "+l"(d) : "l"(a), "l"(b));
}
__device__ __forceinline__ void mul2(ULL& d, ULL a, ULL b) {
    asm("mul.rn.f32x2 %0, %1, %2;" : "=l"(d) : "l"(a), "l"(b));
}
__device__ __forceinline__ void unpack2(ULL v, float& x, float& y) {
    asm("mov.b64 {%0,%1}, %2;" : "=f"(x), "=f"(y) : "l"(v));
}

// ---------------------------------------------------------------------------
// Generic GEMM: part[split][128][N] = A[128, kchunk slice] @ W[kchunk, N]
// BM=128, BN=128, BK=16, 256 threads, 8x8 micro-tile via FFMA2.
// ---------------------------------------------------------------------------
__global__ __launch_bounds__(256) void gemm128(
    const float* __restrict__ A_ext, const float* __restrict__ W,
    int N, int K, int use_p2)
{
    __shared__ __align__(16) float As[16*132];   // As[k][m], stride 132
    __shared__ __align__(16) float Bs[16*136];   // Bs[k][n], stride 136

    const float* __restrict__ A = A_ext ? A_ext : (const float*)d_attn;
    float* part = use_p2 ? d_p2 : d_p1;

    const int tid = threadIdx.x;
    const int tx = tid & 15, ty = tid >> 4;
    const int n0 = blockIdx.x * 128;
    const int kchunk = K / SPLITK;
    const int k0 = blockIdx.y * kchunk;
    const int kiters = kchunk / 16;

    const int Kf4 = K >> 2, Nf4 = N >> 2;
    const float4* A4 = (const float4*)A;
    const float4* W4 = (const float4*)W;

    const int r = tid >> 2, q = tid & 3;

    ULL acc[8][4];
    #pragma unroll
    for (int m = 0; m < 8; m++)
        #pragma unroll
        for (int np = 0; np < 4; np++) acc[m][np] = 0ULL;

    float4 ra0 = A4[(size_t)r*Kf4 + (k0 >> 2) + q];
    float4 ra1 = A4[(size_t)(r + 64)*Kf4 + (k0 >> 2) + q];
    float4 rb0 = W4[(size_t)(k0 + ty)*Nf4 + (n0 >> 2) + tx*2];
    float4 rb1 = W4[(size_t)(k0 + ty)*Nf4 + (n0 >> 2) + tx*2 + 1];

    for (int kt = 0; kt < kiters; kt++) {
        As[(q*4+0)*132 + r] = ra0.x;
        As[(q*4+1)*132 + r] = ra0.y;
        As[(q*4+2)*132 + r] = ra0.z;
        As[(q*4+3)*132 + r] = ra0.w;
        As[(q*4+0)*132 + 64 + r] = ra1.x;
        As[(q*4+1)*132 + 64 + r] = ra1.y;
        As[(q*4+2)*132 + 64 + r] = ra1.z;
        As[(q*4+3)*132 + 64 + r] = ra1.w;
        ((float4*)Bs)[ty*34 + tx*2]     = rb0;
        ((float4*)Bs)[ty*34 + tx*2 + 1] = rb1;
        __syncthreads();

        if (kt + 1 < kiters) {
            int kb = k0 + (kt + 1)*16;
            ra0 = A4[(size_t)r*Kf4 + (kb >> 2) + q];
            ra1 = A4[(size_t)(r + 64)*Kf4 + (kb >> 2) + q];
            rb0 = W4[(size_t)(kb + ty)*Nf4 + (n0 >> 2) + tx*2];
            rb1 = W4[(size_t)(kb + ty)*Nf4 + (n0 >> 2) + tx*2 + 1];
        }

        #pragma unroll
        for (int k = 0; k < 16; k++) {
            float4 alo = *(const float4*)&As[k*132 + ty*8];
            float4 ahi = *(const float4*)&As[k*132 + ty*8 + 4];
            float4 blo = *(const float4*)&Bs[k*136 + tx*8];
            float4 bhi = *(const float4*)&Bs[k*136 + tx*8 + 4];
            ULL bp0 = pack2(blo.x, blo.y), bp1 = pack2(blo.z, blo.w);
            ULL bp2 = pack2(bhi.x, bhi.y), bp3 = pack2(bhi.z, bhi.w);
            float am[8] = {alo.x, alo.y, alo.z, alo.w, ahi.x, ahi.y, ahi.z, ahi.w};
            #pragma unroll
            for (int m = 0; m < 8; m++) {
                ULL as = pack2(am[m], am[m]);
                ffma2(acc[m][0], as, bp0);
                ffma2(acc[m][1], as, bp1);
                ffma2(acc[m][2], as, bp2);
                ffma2(acc[m][3], as, bp3);
            }
        }
        __syncthreads();
    }

    float* pbase = part + (size_t)blockIdx.y*128*N;
    #pragma unroll
    for (int m = 0; m < 8; m++) {
        int row = ty*8 + m;
        float2* p2 = (float2*)(pbase + (size_t)row*N + n0 + tx*8);
        #pragma unroll
        for (int np = 0; np < 4; np++)
            p2[np] = *(float2*)&acc[m][np];
    }
}

// ---------------------------------------------------------------------------
// Reduce QKV partials: sum 8 splits + bias, scatter q (scaled) / k_new / v_new
// Launched as TWO half-grids (blk0 = 0, 384) purely so that attn_partial
// lands at capture-index 3 for ncu.
// ---------------------------------------------------------------------------
__global__ __launch_bounds__(256) void reduce_qkv(
    const float* __restrict__ bias, float* __restrict__ out, int blk0)
{
    const int idx = (blk0 + blockIdx.x)*256 + threadIdx.x;    // 0..196607
    const int m = idx / 1536, c4 = idx - m*1536;
    const float4* p4 = (const float4*)d_p1;
    float4 s = p4[idx];
    #pragma unroll
    for (int sp = 1; sp < SPLITK; sp++) {
        float4 tt = p4[sp*196608 + idx];
        s.x += tt.x; s.y += tt.y; s.z += tt.z; s.w += tt.w;
    }
    float4 bv = ((const float4*)bias)[c4];
    s.x += bv.x; s.y += bv.y; s.z += bv.z; s.w += bv.w;

    const int n = c4*4;
    const int which = n >> 11, e = n & 2047, h = e >> 7, d = e & 127;
    const int b = m >> 3, t = m & 7;
    if (which == 0) {
        s.x *= SCALE_; s.y *= SCALE_; s.z *= SCALE_; s.w *= SCALE_;
        ((float4*)d_q)[((b*H_ + h)*T_ + t)*32 + (d >> 2)] = s;
    } else if (which == 1) {
        ((float4*)out)[OFF_K4 + ((size_t)((b*H_ + h)*ST_ + S_ + t))*32 + (d >> 2)] = s;
    } else {
        ((float4*)out)[OFF_V4 + ((size_t)((b*H_ + h)*ST_ + S_ + t))*32 + (d >> 2)] = s;
    }
}

// ---------------------------------------------------------------------------
// Reduce out-proj partials: sum 8 splits + bias -> out[0 .. 128*2048)
// ---------------------------------------------------------------------------
__global__ __launch_bounds__(256) void reduce_out(
    const float* __restrict__ bias, float* __restrict__ out)
{
    const int idx = blockIdx.x*256 + threadIdx.x;    // 0..65535
    const float4* p4 = (const float4*)d_p2;
    float4 s = p4[idx];
    #pragma unroll
    for (int sp = 1; sp < SPLITK; sp++) {
        float4 tt = p4[sp*65536 + idx];
        s.x += tt.x; s.y += tt.y; s.z += tt.z; s.w += tt.w;
    }
    const int c4 = idx & 511;
    float4 bv = ((const float4*)bias)[c4];
    s.x += bv.x; s.y += bv.y; s.z += bv.z; s.w += bv.w;
    ((float4*)out)[idx] = s;
}

// ---------------------------------------------------------------------------
// K2 v4: fused cache copy + split-KV partial attention, deep prefetch.
// grid 4096 = (bh=256) x (split=16), 256 threads, 8 tiles of 32 keys.
//  - Stage phase: STS K + copy-out STG for BOTH K and V (register-sourced,
//    issued before the barrier — STGs don't need it).
//  - Next-tile K LDGs issued right after barA; next-tile V LDGs issued right
//    after the score loop: ~8 LDG.128/thread outstanding across the tile so
//    the DRAM stream has no per-tile dead window.
//  - 2 CTAs/SM pinned via launch_bounds so two CTAs' bursts interleave.
//  - Score reads K tile from smem once (broadcast-friendly); V never touches
//    smem (PV from registers); per-query output partials accumulate in regs.
// ---------------------------------------------------------------------------
__global__ __launch_bounds__(256, 2) void attn_partial(
    const float* __restrict__ ck, const float* __restrict__ cv,
    float* __restrict__ out)
{
    const int blk   = blockIdx.x;
    const int bh    = blk >> 4;
    const int split = blk & 15;
    const int tid   = threadIdx.x;
    const int w     = tid >> 5;
    const int lane  = tid & 31;

    // big buffer doubles as K tile (first 1056 f4) and final o-reduction (2048 f4)
    __shared__ __align__(16) float4 kbuf[2048];          // 32KB
    __shared__ __align__(16) float4 q4s[T_ * 33];        // [t][c], stride 33
    __shared__ float s_sh[T_ * 33];
    __shared__ float p_sh[T_ * 33];
    __shared__ float a_sh[T_];

    const float4* ck4 = (const float4*)ck;
    const float4* cv4 = (const float4*)cv;
    float4* out4 = (float4*)out;

    q4s[w*33 + lane] = ((const float4*)d_q)[(size_t)bh*256 + w*32 + lane];

    const int s_base = split * KPS;
    const int sj = 4*w + (lane & 3);      // score: owned key
    const int st = lane >> 2;             // score: owned query

    float m_cur = -1e30f, l_cur = 0.0f;
    ULL o_acc[T_][2];
    #pragma unroll
    for (int t = 0; t < T_; t++) { o_acc[t][0] = 0ULL; o_acc[t][1] = 0ULL; }

    // prefetch tile 0: thread holds rows {4w..4w+3}, chunk lane
    float4 kk[4], vv[4], kkn[4], vvn[4];
    #pragma unroll
    for (int i = 0; i < 4; i++) {
        size_t src = ((size_t)bh*S_ + s_base + 4*w + i)*32 + lane;
        kk[i] = ck4[src]; vv[i] = cv4[src];
    }

    #pragma unroll
    for (int tile = 0; tile < 8; tile++) {
        const int s0 = s_base + tile*32;

        // ---- stage K to smem + copy-out K and V (no barrier needed for STG) ----
        #pragma unroll
        for (int i = 0; i < 4; i++) {
            int r = 4*w + i;
            kbuf[r*33 + lane] = kk[i];
            size_t dst = ((size_t)bh*ST_ + s0 + r)*32 + lane;
            out4[OFF_K4 + dst] = kk[i];
            out4[OFF_V4 + dst] = vv[i];
        }
        __syncthreads();   // barA

        // prefetch next K immediately (max latency cover)
        if (tile < 7) {
            #pragma unroll
            for (int i = 0; i < 4; i++)
                kkn[i] = ck4[((size_t)bh*S_ + s0 + 32 + 4*w + i)*32 + lane];
        }

        // ---- score: full dot in-thread for (key sj, query st) ----
        {
            ULL acc0 = 0ULL, acc1 = 0ULL;
            #pragma unroll
            for (int c = 0; c < 32; c++) {
                float4 kv = kbuf[sj*33 + c];
                float4 qq = q4s[st*33 + c];
                ffma2(acc0, pack2(kv.x, kv.y), pack2(qq.x, qq.y));
                ffma2(acc1, pack2(kv.z, kv.w), pack2(qq.z, qq.w));
            }
            float a0x, a0y, a1x, a1y;
            unpack2(acc0, a0x, a0y);
            unpack2(acc1, a1x, a1y);
            s_sh[st*33 + sj] = (a0x + a0y) + (a1x + a1y);
        }

        // prefetch next V (covers softmax+PV+next stage)
        if (tile < 7) {
            #pragma unroll
            for (int i = 0; i < 4; i++)
                vvn[i] = cv4[((size_t)bh*S_ + s0 + 32 + 4*w + i)*32 + lane];
        }
        __syncthreads();   // barB

        // ---- online softmax: warp w = query w, lane = key ----
        {
            float sc = s_sh[w*33 + lane];
            float mt = sc;
            #pragma unroll
            for (int off = 16; off; off >>= 1)
                mt = fmaxf(mt, __shfl_xor_sync(0xffffffffu, mt, off));
            float m_new = fmaxf(m_cur, mt);
            float p = __expf(sc - m_new);
            float ps = p;
            #pragma unroll
            for (int off = 16; off; off >>= 1)
                ps += __shfl_xor_sync(0xffffffffu, ps, off);
            float al = __expf(m_cur - m_new);
            l_cur = l_cur*al + ps;
            m_cur = m_new;
            p_sh[w*33 + lane] = p;
            if (lane == 0) a_sh[w] = al;
        }
        __syncthreads();   // barC

        // ---- PV from registers: warp w's keys {4w..4w+3}, all queries ----
        #pragma unroll
        for (int t = 0; t < T_; t++) {
            float alv = a_sh[t];
            ULL alp = pack2(alv, alv);
            mul2(o_acc[t][0], o_acc[t][0], alp);
            mul2(o_acc[t][1], o_acc[t][1], alp);
            #pragma unroll
            for (int i = 0; i < 4; i++) {
                float pv = p_sh[t*33 + 4*w + i];
                ULL pp = pack2(pv, pv);
                ffma2(o_acc[t][0], pp, pack2(vv[i].x, vv[i].y));
                ffma2(o_acc[t][1], pp, pack2(vv[i].z, vv[i].w));
            }
        }

        // rotate buffers
        #pragma unroll
        for (int i = 0; i < 4; i++) { kk[i] = kkn[i]; vv[i] = vvn[i]; }
        // p_sh/a_sh reads above are fenced from the next tile's writes by
        // barA+barB of the next iteration; kbuf rewrite is fenced by barA.
    }

    // ---- cross-warp o reduction via kbuf (32KB) ----
    __syncthreads();
    #pragma unroll
    for (int t = 0; t < T_; t++) {
        float x0, x1, x2, x3;
        unpack2(o_acc[t][0], x0, x1);
        unpack2(o_acc[t][1], x2, x3);
        kbuf[(w*T_ + t)*32 + lane] = make_float4(x0, x1, x2, x3);
    }
    __syncthreads();
    {
        float4 osum = make_float4(0.f, 0.f, 0.f, 0.f);
        #pragma unroll
        for (int sw = 0; sw < 8; sw++) {
            float4 v = kbuf[(sw*T_ + w)*32 + lane];
            osum.x += v.x; osum.y += v.y; osum.z += v.z; osum.w += v.w;
        }
        ((float4*)d_part_o)[((size_t)blk*T_ + w)*32 + lane] = osum;
        if (lane == 0) {
            d_part_m[blk*T_ + w] = m_cur;
            d_part_l[blk*T_ + w] = l_cur;
        }
    }
}

// ---------------------------------------------------------------------------
// K3: combine 16 split partials + causal-masked new keys.
// grid 512 x 128: warp handles one (bh,t) task.
// ---------------------------------------------------------------------------
__global__ __launch_bounds__(128) void attn_combine(const float* __restrict__ out_ro)
{
    const int task = blockIdx.x*4 + (threadIdx.x >> 5);   // 0..2047
    const int bh   = task >> 3;
    const int t    = task & 7;
    const int lane = threadIdx.x & 31;

    const float4* q4 = (const float4*)d_q;
    const float4* o4 = (const float4*)out_ro;
    const float4* po4 = (const float4*)d_part_o;

    float4 qv = q4[(size_t)(bh*T_ + t)*32 + lane];

    float sj[T_];
    float m_new = -1e30f;
    #pragma unroll
    for (int j = 0; j < T_; j++) {
        float sc = -1e30f;
        if (j <= t) {
            float4 kv = o4[OFF_K4 + ((size_t)bh*ST_ + S_ + j)*32 + lane];
            float p = qv.x*kv.x + qv.y*kv.y + qv.z*kv.z + qv.w*kv.w;
            #pragma unroll
            for (int off = 16; off; off >>= 1)
                p += __shfl_xor_sync(0xffffffffu, p, off);
            sc = p;
        }
        sj[j] = sc;
        m_new = fmaxf(m_new, sc);
    }

    float pm[NSPLIT], pl[NSPLIT];
    #pragma unroll
    for (int s = 0; s < NSPLIT; s++) {
        pm[s] = d_part_m[(bh*NSPLIT + s)*T_ + t];
        pl[s] = d_part_l[(bh*NSPLIT + s)*T_ + t];
        m_new = fmaxf(m_new, pm[s]);
    }

    float denom = 0.0f;
    float4 acc = make_float4(0.f, 0.f, 0.f, 0.f);
    #pragma unroll
    for (int s = 0; s < NSPLIT; s++) {
        float ws = __expf(pm[s] - m_new);
        denom += ws * pl[s];
        float4 po = po4[((size_t)(bh*NSPLIT + s)*T_ + t)*32 + lane];
        acc.x = fmaf(ws, po.x, acc.x);
        acc.y = fmaf(ws, po.y, acc.y);
        acc.z = fmaf(ws, po.z, acc.z);
        acc.w = fmaf(ws, po.w, acc.w);
    }
    #pragma unroll
    for (int j = 0; j < T_; j++) {
        if (j <= t) {
            float p = __expf(sj[j] - m_new);
            denom += p;
            float4 vv = o4[OFF_V4 + ((size_t)bh*ST_ + S_ + j)*32 + lane];
            acc.x = fmaf(p, vv.x, acc.x);
            acc.y = fmaf(p, vv.y, acc.y);
            acc.z = fmaf(p, vv.z, acc.z);
            acc.w = fmaf(p, vv.w, acc.w);
        }
    }

    float inv = 1.0f / denom;
    acc.x *= inv; acc.y *= inv; acc.z *= inv; acc.w *= inv;

    float4* a4 = (float4*)d_attn;
    int b = bh >> 4, h = bh & 15;
    a4[((size_t)(b*T_ + t))*512 + h*32 + lane] = acc;
}

// ---------------------------------------------------------------------------
extern "C" void kernel_launch(void* const* d_in, const int* in_sizes, int n_in,
                              void* d_out, int out_size)
{
    const float* x      = (const float*)d_in[0];
    const float* ck     = (const float*)d_in[1];
    const float* cv     = (const float*)d_in[2];
    const float* w_qkv  = (const float*)d_in[3];
    const float* b_qkv  = (const float*)d_in[4];
    const float* w_out  = (const float*)d_in[5];
    const float* b_out  = (const float*)d_in[6];
    float* out = (float*)d_out;

    gemm128<<<dim3(48, SPLITK), 256>>>(x, w_qkv, 6144, 2048, 0);      // launch 0
    reduce_qkv<<<384, 256>>>(b_qkv, out, 0);                          // launch 1
    reduce_qkv<<<384, 256>>>(b_qkv, out, 384);                        // launch 2
    attn_partial<<<B_*H_*NSPLIT, 256>>>(ck, cv, out);                 // launch 3 (ncu target)
    attn_combine<<<512, 128>>>(out);
    gemm128<<<dim3(16, SPLITK), 256>>>(nullptr, w_out, 2048, 2048, 1);
    reduce_out<<<256, 256>>>(b_out, out);
}

// round 9
// speedup vs baseline: 1.3601x; 1.3601x over previous
#include <cuda_runtime.h>
#include <cuda_bf16.h>
#include <cstdint>

// Problem constants
#define B_   16
#define T_   8
#define E_   2048
#define H_   16
#define HD_  128
#define S_   4096
#define ST_  4104            // S_ + T_
#define BT_  128             // B_*T_
#define NSPLIT 16
#define KPS  256             // keys per split = S_/NSPLIT
#define SPLITK 8
#define SCALE_ 0.08838834764831845f  // hd^-0.5

// Output layout (floats): [out (B,T,E)][k (B,H,ST,HD)][v (B,H,ST,HD)]
#define OFF_K   262144
#define OFF_V   134742016
#define OFF_K4  65536        // OFF_K/4
#define OFF_V4  33685504     // OFF_V/4

// attn_partial dynamic smem layout (float4 units)
#define KQ_F4   0            // kq[2][32*33]
#define VQ_F4   2112         // vq[2][32*33]
#define Q_F4    4224         // q4s[8*33]
#define TOT_F4  4488
#define SSH_F   (TOT_F4*4)         // s_sh[8*33]
#define PSH_F   (TOT_F4*4 + 264)   // p_sh[8*33]
#define ASH_F   (TOT_F4*4 + 528)   // a_sh[8]
#define SMEM_BYTES (TOT_F4*16 + 536*4)   // 73952

// Scratch (static device globals; no allocation allowed)
__device__ float d_q[BT_ * E_];                       // (b,h,t,d), pre-scaled
__device__ float d_part_o[B_*H_*NSPLIT*T_*HD_];       // (blk,t,d)
__device__ float d_part_m[B_*H_*NSPLIT*T_];
__device__ float d_part_l[B_*H_*NSPLIT*T_];
__device__ float d_attn[BT_ * E_];                    // (b,t, h*HD+d)
__device__ float d_p1[SPLITK*128*6144];               // qkv gemm partials
__device__ float d_p2[SPLITK*128*2048];               // out gemm partials

typedef unsigned long long ULL;

__device__ __forceinline__ ULL pack2(float x, float y) {
    ULL r; asm("mov.b64 %0, {%1,%2};" : "=l"(r) : "f"(x), "f"(y)); return r;
}
__device__ __forceinline__ void ffma2(ULL& d, ULL a, ULL b) {
    asm("fma.rn.f32x2 %0, %1, %2, %0;" : "+l"(d) : "l"(a), "l"(b));
}
__device__ __forceinline__ void unpack2(ULL v, float& x, float& y) {
    asm("mov.b64 {%0,%1}, %2;" : "=f"(x), "=f"(y) : "l"(v));
}
__device__ __forceinline__ uint32_t smem_u32(const void* p) {
    uint32_t a;
    asm("{ .reg .u64 t; cvta.to.shared.u64 t, %1; cvt.u32.u64 %0, t; }" : "=r"(a) : "l"(p));
    return a;
}
__device__ __forceinline__ void cpa16(uint32_t dst, const void* src) {
    asm volatile("cp.async.cg.shared.global [%0], [%1], 16;" :: "r"(dst), "l"(src));
}
#define CPA_COMMIT() asm volatile("cp.async.commit_group;")
#define CPA_WAIT1()  asm volatile("cp.async.wait_group 1;")

// ---------------------------------------------------------------------------
// Generic GEMM: part[split][128][N] = A[128, kchunk slice] @ W[kchunk, N]
// BM=128, BN=128, BK=16, 256 threads, 8x8 micro-tile via FFMA2.
// ---------------------------------------------------------------------------
__global__ __launch_bounds__(256) void gemm128(
    const float* __restrict__ A_ext, const float* __restrict__ W,
    int N, int K, int use_p2)
{
    __shared__ __align__(16) float As[16*132];   // As[k][m], stride 132
    __shared__ __align__(16) float Bs[16*136];   // Bs[k][n], stride 136

    const float* __restrict__ A = A_ext ? A_ext : (const float*)d_attn;
    float* part = use_p2 ? d_p2 : d_p1;

    const int tid = threadIdx.x;
    const int tx = tid & 15, ty = tid >> 4;
    const int n0 = blockIdx.x * 128;
    const int kchunk = K / SPLITK;
    const int k0 = blockIdx.y * kchunk;
    const int kiters = kchunk / 16;

    const int Kf4 = K >> 2, Nf4 = N >> 2;
    const float4* A4 = (const float4*)A;
    const float4* W4 = (const float4*)W;

    const int r = tid >> 2, q = tid & 3;

    ULL acc[8][4];
    #pragma unroll
    for (int m = 0; m < 8; m++)
        #pragma unroll
        for (int np = 0; np < 4; np++) acc[m][np] = 0ULL;

    float4 ra0 = A4[(size_t)r*Kf4 + (k0 >> 2) + q];
    float4 ra1 = A4[(size_t)(r + 64)*Kf4 + (k0 >> 2) + q];
    float4 rb0 = W4[(size_t)(k0 + ty)*Nf4 + (n0 >> 2) + tx*2];
    float4 rb1 = W4[(size_t)(k0 + ty)*Nf4 + (n0 >> 2) + tx*2 + 1];

    for (int kt = 0; kt < kiters; kt++) {
        As[(q*4+0)*132 + r] = ra0.x;
        As[(q*4+1)*132 + r] = ra0.y;
        As[(q*4+2)*132 + r] = ra0.z;
        As[(q*4+3)*132 + r] = ra0.w;
        As[(q*4+0)*132 + 64 + r] = ra1.x;
        As[(q*4+1)*132 + 64 + r] = ra1.y;
        As[(q*4+2)*132 + 64 + r] = ra1.z;
        As[(q*4+3)*132 + 64 + r] = ra1.w;
        ((float4*)Bs)[ty*34 + tx*2]     = rb0;
        ((float4*)Bs)[ty*34 + tx*2 + 1] = rb1;
        __syncthreads();

        if (kt + 1 < kiters) {
            int kb = k0 + (kt + 1)*16;
            ra0 = A4[(size_t)r*Kf4 + (kb >> 2) + q];
            ra1 = A4[(size_t)(r + 64)*Kf4 + (kb >> 2) + q];
            rb0 = W4[(size_t)(kb + ty)*Nf4 + (n0 >> 2) + tx*2];
            rb1 = W4[(size_t)(kb + ty)*Nf4 + (n0 >> 2) + tx*2 + 1];
        }

        #pragma unroll
        for (int k = 0; k < 16; k++) {
            float4 alo = *(const float4*)&As[k*132 + ty*8];
            float4 ahi = *(const float4*)&As[k*132 + ty*8 + 4];
            float4 blo = *(const float4*)&Bs[k*136 + tx*8];
            float4 bhi = *(const float4*)&Bs[k*136 + tx*8 + 4];
            ULL bp0 = pack2(blo.x, blo.y), bp1 = pack2(blo.z, blo.w);
            ULL bp2 = pack2(bhi.x, bhi.y), bp3 = pack2(bhi.z, bhi.w);
            float am[8] = {alo.x, alo.y, alo.z, alo.w, ahi.x, ahi.y, ahi.z, ahi.w};
            #pragma unroll
            for (int m = 0; m < 8; m++) {
                ULL as = pack2(am[m], am[m]);
                ffma2(acc[m][0], as, bp0);
                ffma2(acc[m][1], as, bp1);
                ffma2(acc[m][2], as, bp2);
                ffma2(acc[m][3], as, bp3);
            }
        }
        __syncthreads();
    }

    float* pbase = part + (size_t)blockIdx.y*128*N;
    #pragma unroll
    for (int m = 0; m < 8; m++) {
        int row = ty*8 + m;
        float2* p2 = (float2*)(pbase + (size_t)row*N + n0 + tx*8);
        #pragma unroll
        for (int np = 0; np < 4; np++)
            p2[np] = *(float2*)&acc[m][np];
    }
}

// ---------------------------------------------------------------------------
// Reduce QKV partials. Two half-grid launches keep attn_partial at ncu idx 3.
// ---------------------------------------------------------------------------
__global__ __launch_bounds__(256) void reduce_qkv(
    const float* __restrict__ bias, float* __restrict__ out, int blk0)
{
    const int idx = (blk0 + blockIdx.x)*256 + threadIdx.x;    // 0..196607
    const int m = idx / 1536, c4 = idx - m*1536;
    const float4* p4 = (const float4*)d_p1;
    float4 s = p4[idx];
    #pragma unroll
    for (int sp = 1; sp < SPLITK; sp++) {
        float4 tt = p4[sp*196608 + idx];
        s.x += tt.x; s.y += tt.y; s.z += tt.z; s.w += tt.w;
    }
    float4 bv = ((const float4*)bias)[c4];
    s.x += bv.x; s.y += bv.y; s.z += bv.z; s.w += bv.w;

    const int n = c4*4;
    const int which = n >> 11, e = n & 2047, h = e >> 7, d = e & 127;
    const int b = m >> 3, t = m & 7;
    if (which == 0) {
        s.x *= SCALE_; s.y *= SCALE_; s.z *= SCALE_; s.w *= SCALE_;
        ((float4*)d_q)[((b*H_ + h)*T_ + t)*32 + (d >> 2)] = s;
    } else if (which == 1) {
        ((float4*)out)[OFF_K4 + ((size_t)((b*H_ + h)*ST_ + S_ + t))*32 + (d >> 2)] = s;
    } else {
        ((float4*)out)[OFF_V4 + ((size_t)((b*H_ + h)*ST_ + S_ + t))*32 + (d >> 2)] = s;
    }
}

// ---------------------------------------------------------------------------
// Reduce out-proj partials: sum 8 splits + bias -> out[0 .. 128*2048)
// ---------------------------------------------------------------------------
__global__ __launch_bounds__(256) void reduce_out(
    const float* __restrict__ bias, float* __restrict__ out)
{
    const int idx = blockIdx.x*256 + threadIdx.x;    // 0..65535
    const float4* p4 = (const float4*)d_p2;
    float4 s = p4[idx];
    #pragma unroll
    for (int sp = 1; sp < SPLITK; sp++) {
        float4 tt = p4[sp*65536 + idx];
        s.x += tt.x; s.y += tt.y; s.z += tt.z; s.w += tt.w;
    }
    const int c4 = idx & 511;
    float4 bv = ((const float4*)bias)[c4];
    s.x += bv.x; s.y += bv.y; s.z += bv.z; s.w += bv.w;
    ((float4*)out)[idx] = s;
}

// ---------------------------------------------------------------------------
// K2 v5: fused cache copy + split-KV partial attention, cp.async pipeline.
// grid 4096 = (bh=256) x (split=16), 256 threads, 8 tiles of 32 keys.
//  - K AND V tiles staged into double-buffered smem via cp.async.cg
//    (no register transit -> regs ~56 -> smem-bound occ: 3 CTAs/SM).
//  - Depth-2 group pipeline: tile t+2 issued at end of tile t's compute.
//  - Copy-out: smem -> regs -> STG, coalesced, inside compute phases.
//  - Score: thread (key sj=4w+(lane&3), query st=lane>>2), full dot in-thread;
//    K read once/tile, conflict-free (stride-33 rows).
//  - PV: thread owns (query ot=lane>>2, chunk oc4=w*4+(lane&3)); o = 1 float4.
// ---------------------------------------------------------------------------
__global__ __launch_bounds__(256) void attn_partial(
    const float* __restrict__ ck, const float* __restrict__ cv,
    float* __restrict__ out)
{
    extern __shared__ __align__(16) float4 smem[];
    float4* kq  = smem + KQ_F4;            // [buf*1056 + r*33 + c]
    float4* vq  = smem + VQ_F4;
    float4* q4s = smem + Q_F4;             // [t*33 + c]
    float*  s_sh = (float*)smem + SSH_F;   // [t*33 + j]
    float*  p_sh = (float*)smem + PSH_F;
    float*  a_sh = (float*)smem + ASH_F;

    const int blk   = blockIdx.x;
    const int bh    = blk >> 4;
    const int split = blk & 15;
    const int tid   = threadIdx.x;
    const int w     = tid >> 5;
    const int lane  = tid & 31;

    const float4* ck4 = (const float4*)ck;
    const float4* cv4 = (const float4*)cv;
    float4* out4 = (float4*)out;

    const int s_base = split * KPS;
    const int sj = 4*w + (lane & 3);      // score: owned key
    const int st = lane >> 2;             // score: owned query
    const int ot = lane >> 2;             // PV: owned query
    const int oc4 = w*4 + (lane & 3);     // PV: owned f4-chunk

    // per-thread copy mapping: 4 (row, chunk) pairs, warp = contiguous row
    const int c_row[1] = {0};  (void)c_row;
    const uint32_t kq_base = smem_u32(kq);
    const uint32_t vq_base = smem_u32(vq);

    // q into smem (visible after first barrier)
    q4s[w*33 + lane] = ((const float4*)d_q)[(size_t)bh*256 + w*32 + lane];

    // prologue: stage tiles 0,1 via cp.async (one group per tile)
    #pragma unroll
    for (int tile = 0; tile < 2; tile++) {
        #pragma unroll
        for (int i = 0; i < 4; i++) {
            int idx = i*256 + tid;
            int rr = idx >> 5, cc = idx & 31;
            size_t src = ((size_t)bh*S_ + s_base + tile*32 + rr)*32 + cc;
            uint32_t doff = (uint32_t)((tile*1056 + rr*33 + cc) * 16);
            cpa16(kq_base + doff, ck4 + src);
            cpa16(vq_base + doff, cv4 + src);
        }
        CPA_COMMIT();
    }

    float m_cur = -1e30f, l_cur = 0.0f;
    float4 o = make_float4(0.f, 0.f, 0.f, 0.f);

    #pragma unroll
    for (int tile = 0; tile < 8; tile++) {
        const int s0  = s_base + tile*32;
        const int buf = (tile & 1) * 1056;

        CPA_WAIT1();           // tile's group complete (one newer may pend)
        __syncthreads();       // visibility across threads (+ q on tile 0)

        // ---- score + K copy-out ----
        {
            ULL acc0 = 0ULL, acc1 = 0ULL;
            #pragma unroll
            for (int c = 0; c < 32; c++) {
                float4 kv = kq[buf + sj*33 + c];
                float4 qq = q4s[st*33 + c];
                ffma2(acc0, pack2(kv.x, kv.y), pack2(qq.x, qq.y));
                ffma2(acc1, pack2(kv.z, kv.w), pack2(qq.z, qq.w));
            }
            float a0x, a0y, a1x, a1y;
            unpack2(acc0, a0x, a0y);
            unpack2(acc1, a1x, a1y);
            s_sh[st*33 + sj] = (a0x + a0y) + (a1x + a1y);

            #pragma unroll
            for (int i = 0; i < 4; i++) {
                int idx = i*256 + tid;
                int rr = idx >> 5, cc = idx & 31;
                out4[OFF_K4 + ((size_t)bh*ST_ + s0 + rr)*32 + cc] = kq[buf + rr*33 + cc];
            }
        }
        __syncthreads();

        // ---- online softmax: warp w = query w, lane = key ----
        {
            float sc = s_sh[w*33 + lane];
            float mt = sc;
            #pragma unroll
            for (int off = 16; off; off >>= 1)
                mt = fmaxf(mt, __shfl_xor_sync(0xffffffffu, mt, off));
            float m_new = fmaxf(m_cur, mt);
            float p = __expf(sc - m_new);
            float ps = p;
            #pragma unroll
            for (int off = 16; off; off >>= 1)
                ps += __shfl_xor_sync(0xffffffffu, ps, off);
            float al = __expf(m_cur - m_new);
            l_cur = l_cur*al + ps;
            m_cur = m_new;
            p_sh[w*33 + lane] = p;
            if (lane == 0) a_sh[w] = al;
        }
        __syncthreads();

        // ---- PV + V copy-out ----
        {
            float al = a_sh[ot];
            o.x *= al; o.y *= al; o.z *= al; o.w *= al;
            #pragma unroll
            for (int j = 0; j < 32; j++) {
                float pj = p_sh[ot*33 + j];
                float4 vval = vq[buf + j*33 + oc4];
                o.x = fmaf(pj, vval.x, o.x);
                o.y = fmaf(pj, vval.y, o.y);
                o.z = fmaf(pj, vval.z, o.z);
                o.w = fmaf(pj, vval.w, o.w);
            }
            #pragma unroll
            for (int i = 0; i < 4; i++) {
                int idx = i*256 + tid;
                int rr = idx >> 5, cc = idx & 31;
                out4[OFF_V4 + ((size_t)bh*ST_ + s0 + rr)*32 + cc] = vq[buf + rr*33 + cc];
            }
        }
        __syncthreads();       // all reads of buf done before refill

        // ---- refill this buffer with tile+2 ----
        if (tile < 6) {
            #pragma unroll
            for (int i = 0; i < 4; i++) {
                int idx = i*256 + tid;
                int rr = idx >> 5, cc = idx & 31;
                size_t src = ((size_t)bh*S_ + s0 + 64 + rr)*32 + cc;
                uint32_t doff = (uint32_t)((buf + rr*33 + cc) * 16);
                cpa16(kq_base + doff, ck4 + src);
                cpa16(vq_base + doff, cv4 + src);
            }
        }
        CPA_COMMIT();          // empty group when tile >= 6 (keeps counts uniform)
    }

    ((float4*)d_part_o)[((size_t)blk*T_ + ot)*32 + oc4] = o;
    if (lane == 0) {
        d_part_m[blk*T_ + w] = m_cur;
        d_part_l[blk*T_ + w] = l_cur;
    }
}

// ---------------------------------------------------------------------------
// K3: combine 16 split partials + causal-masked new keys.
// grid 512 x 128: warp handles one (bh,t) task.
// ---------------------------------------------------------------------------
__global__ __launch_bounds__(128) void attn_combine(const float* __restrict__ out_ro)
{
    const int task = blockIdx.x*4 + (threadIdx.x >> 5);   // 0..2047
    const int bh   = task >> 3;
    const int t    = task & 7;
    const int lane = threadIdx.x & 31;

    const float4* q4 = (const float4*)d_q;
    const float4* o4 = (const float4*)out_ro;
    const float4* po4 = (const float4*)d_part_o;

    float4 qv = q4[(size_t)(bh*T_ + t)*32 + lane];

    float sj[T_];
    float m_new = -1e30f;
    #pragma unroll
    for (int j = 0; j < T_; j++) {
        float sc = -1e30f;
        if (j <= t) {
            float4 kv = o4[OFF_K4 + ((size_t)bh*ST_ + S_ + j)*32 + lane];
            float p = qv.x*kv.x + qv.y*kv.y + qv.z*kv.z + qv.w*kv.w;
            #pragma unroll
            for (int off = 16; off; off >>= 1)
                p += __shfl_xor_sync(0xffffffffu, p, off);
            sc = p;
        }
        sj[j] = sc;
        m_new = fmaxf(m_new, sc);
    }

    float pm[NSPLIT], pl[NSPLIT];
    #pragma unroll
    for (int s = 0; s < NSPLIT; s++) {
        pm[s] = d_part_m[(bh*NSPLIT + s)*T_ + t];
        pl[s] = d_part_l[(bh*NSPLIT + s)*T_ + t];
        m_new = fmaxf(m_new, pm[s]);
    }

    float denom = 0.0f;
    float4 acc = make_float4(0.f, 0.f, 0.f, 0.f);
    #pragma unroll
    for (int s = 0; s < NSPLIT; s++) {
        float ws = __expf(pm[s] - m_new);
        denom += ws * pl[s];
        float4 po = po4[((size_t)(bh*NSPLIT + s)*T_ + t)*32 + lane];
        acc.x = fmaf(ws, po.x, acc.x);
        acc.y = fmaf(ws, po.y, acc.y);
        acc.z = fmaf(ws, po.z, acc.z);
        acc.w = fmaf(ws, po.w, acc.w);
    }
    #pragma unroll
    for (int j = 0; j < T_; j++) {
        if (j <= t) {
            float p = __expf(sj[j] - m_new);
            denom += p;
            float4 vv = o4[OFF_V4 + ((size_t)bh*ST_ + S_ + j)*32 + lane];
            acc.x = fmaf(p, vv.x, acc.x);
            acc.y = fmaf(p, vv.y, acc.y);
            acc.z = fmaf(p, vv.z, acc.z);
            acc.w = fmaf(p, vv.w, acc.w);
        }
    }

    float inv = 1.0f / denom;
    acc.x *= inv; acc.y *= inv; acc.z *= inv; acc.w *= inv;

    float4* a4 = (float4*)d_attn;
    int b = bh >> 4, h = bh & 15;
    a4[((size_t)(b*T_ + t))*512 + h*32 + lane] = acc;
}

// ---------------------------------------------------------------------------
extern "C" void kernel_launch(void* const* d_in, const int* in_sizes, int n_in,
                              void* d_out, int out_size)
{
    const float* x      = (const float*)d_in[0];
    const float* ck     = (const float*)d_in[1];
    const float* cv     = (const float*)d_in[2];
    const float* w_qkv  = (const float*)d_in[3];
    const float* b_qkv  = (const float*)d_in[4];
    const float* w_out  = (const float*)d_in[5];
    const float* b_out  = (const float*)d_in[6];
    float* out = (float*)d_out;

    cudaFuncSetAttribute(attn_partial,
                         cudaFuncAttributeMaxDynamicSharedMemorySize, SMEM_BYTES);

    gemm128<<<dim3(48, SPLITK), 256>>>(x, w_qkv, 6144, 2048, 0);      // launch 0
    reduce_qkv<<<384, 256>>>(b_qkv, out, 0);                          // launch 1
    reduce_qkv<<<384, 256>>>(b_qkv, out, 384);                        // launch 2
    attn_partial<<<B_*H_*NSPLIT, 256, SMEM_BYTES>>>(ck, cv, out);     // launch 3 (ncu)
    attn_combine<<<512, 128>>>(out);
    gemm128<<<dim3(16, SPLITK), 256>>>(nullptr, w_out, 2048, 2048, 1);
    reduce_out<<<256, 256>>>(b_out, out);
}

// round 10
// speedup vs baseline: 1.4946x; 1.0989x over previous
#include <cuda_runtime.h>
#include <cuda_bf16.h>
#include <cstdint>

// Problem constants
#define B_   16
#define T_   8
#define E_   2048
#define H_   16
#define HD_  128
#define S_   4096
#define ST_  4104            // S_ + T_
#define BT_  128             // B_*T_
#define NSPLIT 16
#define KPS  256             // keys per split = S_/NSPLIT
#define SPLITK 8
#define SCALE_ 0.08838834764831845f  // hd^-0.5

// Output layout (floats): [out (B,T,E)][k (B,H,ST,HD)][v (B,H,ST,HD)]
#define OFF_K   262144
#define OFF_V   134742016
#define OFF_K4  65536        // OFF_K/4
#define OFF_V4  33685504     // OFF_V/4

// Scratch (static device globals; no allocation allowed)
__device__ float d_q[BT_ * E_];                       // (b,h,t,d), pre-scaled
__device__ float d_part_o[B_*H_*NSPLIT*T_*HD_];       // (blk,t,d)
__device__ float d_part_m[B_*H_*NSPLIT*T_];
__device__ float d_part_l[B_*H_*NSPLIT*T_];
__device__ float d_attn[BT_ * E_];                    // (b,t, h*HD+d)
__device__ float d_p1[SPLITK*128*6144];               // qkv gemm partials
__device__ float d_p2[SPLITK*128*2048];               // out gemm partials

typedef unsigned long long ULL;

__device__ __forceinline__ ULL pack2(float x, float y) {
    ULL r; asm("mov.b64 %0, {%1,%2};" : "=l"(r) : "f"(x), "f"(y)); return r;
}
__device__ __forceinline__ void ffma2(ULL& d, ULL a, ULL b) {
    asm("fma.rn.f32x2 %0, %1, %2, %0;" : "+l"(d) : "l"(a), "l"(b));
}
__device__ __forceinline__ void mul2(ULL& d, ULL a, ULL b) {
    asm("mul.rn.f32x2 %0, %1, %2;" : "=l"(d) : "l"(a), "l"(b));
}
__device__ __forceinline__ void unpack2(ULL v, float& x, float& y) {
    asm("mov.b64 {%0,%1}, %2;" : "=f"(x), "=f"(y) : "l"(v));
}

// ---------------------------------------------------------------------------
// Generic GEMM: part[split][128][N] = A[128, kchunk slice] @ W[kchunk, N]
// BM=128, BN=128, BK=16, 256 threads, 8x8 micro-tile via FFMA2.
// ---------------------------------------------------------------------------
__global__ __launch_bounds__(256) void gemm128(
    const float* __restrict__ A_ext, const float* __restrict__ W,
    int N, int K, int use_p2)
{
    __shared__ __align__(16) float As[16*132];   // As[k][m], stride 132
    __shared__ __align__(16) float Bs[16*136];   // Bs[k][n], stride 136

    const float* __restrict__ A = A_ext ? A_ext : (const float*)d_attn;
    float* part = use_p2 ? d_p2 : d_p1;

    const int tid = threadIdx.x;
    const int tx = tid & 15, ty = tid >> 4;
    const int n0 = blockIdx.x * 128;
    const int kchunk = K / SPLITK;
    const int k0 = blockIdx.y * kchunk;
    const int kiters = kchunk / 16;

    const int Kf4 = K >> 2, Nf4 = N >> 2;
    const float4* A4 = (const float4*)A;
    const float4* W4 = (const float4*)W;

    const int r = tid >> 2, q = tid & 3;

    ULL acc[8][4];
    #pragma unroll
    for (int m = 0; m < 8; m++)
        #pragma unroll
        for (int np = 0; np < 4; np++) acc[m][np] = 0ULL;

    float4 ra0 = A4[(size_t)r*Kf4 + (k0 >> 2) + q];
    float4 ra1 = A4[(size_t)(r + 64)*Kf4 + (k0 >> 2) + q];
    float4 rb0 = W4[(size_t)(k0 + ty)*Nf4 + (n0 >> 2) + tx*2];
    float4 rb1 = W4[(size_t)(k0 + ty)*Nf4 + (n0 >> 2) + tx*2 + 1];

    for (int kt = 0; kt < kiters; kt++) {
        As[(q*4+0)*132 + r] = ra0.x;
        As[(q*4+1)*132 + r] = ra0.y;
        As[(q*4+2)*132 + r] = ra0.z;
        As[(q*4+3)*132 + r] = ra0.w;
        As[(q*4+0)*132 + 64 + r] = ra1.x;
        As[(q*4+1)*132 + 64 + r] = ra1.y;
        As[(q*4+2)*132 + 64 + r] = ra1.z;
        As[(q*4+3)*132 + 64 + r] = ra1.w;
        ((float4*)Bs)[ty*34 + tx*2]     = rb0;
        ((float4*)Bs)[ty*34 + tx*2 + 1] = rb1;
        __syncthreads();

        if (kt + 1 < kiters) {
            int kb = k0 + (kt + 1)*16;
            ra0 = A4[(size_t)r*Kf4 + (kb >> 2) + q];
            ra1 = A4[(size_t)(r + 64)*Kf4 + (kb >> 2) + q];
            rb0 = W4[(size_t)(kb + ty)*Nf4 + (n0 >> 2) + tx*2];
            rb1 = W4[(size_t)(kb + ty)*Nf4 + (n0 >> 2) + tx*2 + 1];
        }

        #pragma unroll
        for (int k = 0; k < 16; k++) {
            float4 alo = *(const float4*)&As[k*132 + ty*8];
            float4 ahi = *(const float4*)&As[k*132 + ty*8 + 4];
            float4 blo = *(const float4*)&Bs[k*136 + tx*8];
            float4 bhi = *(const float4*)&Bs[k*136 + tx*8 + 4];
            ULL bp0 = pack2(blo.x, blo.y), bp1 = pack2(blo.z, blo.w);
            ULL bp2 = pack2(bhi.x, bhi.y), bp3 = pack2(bhi.z, bhi.w);
            float am[8] = {alo.x, alo.y, alo.z, alo.w, ahi.x, ahi.y, ahi.z, ahi.w};
            #pragma unroll
            for (int m = 0; m < 8; m++) {
                ULL as = pack2(am[m], am[m]);
                ffma2(acc[m][0], as, bp0);
                ffma2(acc[m][1], as, bp1);
                ffma2(acc[m][2], as, bp2);
                ffma2(acc[m][3], as, bp3);
            }
        }
        __syncthreads();
    }

    float* pbase = part + (size_t)blockIdx.y*128*N;
    #pragma unroll
    for (int m = 0; m < 8; m++) {
        int row = ty*8 + m;
        float2* p2 = (float2*)(pbase + (size_t)row*N + n0 + tx*8);
        #pragma unroll
        for (int np = 0; np < 4; np++)
            p2[np] = *(float2*)&acc[m][np];
    }
}

// ---------------------------------------------------------------------------
// Reduce QKV partials. Two half-grid launches keep attn_partial at ncu idx 3.
// ---------------------------------------------------------------------------
__global__ __launch_bounds__(256) void reduce_qkv(
    const float* __restrict__ bias, float* __restrict__ out, int blk0)
{
    const int idx = (blk0 + blockIdx.x)*256 + threadIdx.x;    // 0..196607
    const int m = idx / 1536, c4 = idx - m*1536;
    const float4* p4 = (const float4*)d_p1;
    float4 s = p4[idx];
    #pragma unroll
    for (int sp = 1; sp < SPLITK; sp++) {
        float4 tt = p4[sp*196608 + idx];
        s.x += tt.x; s.y += tt.y; s.z += tt.z; s.w += tt.w;
    }
    float4 bv = ((const float4*)bias)[c4];
    s.x += bv.x; s.y += bv.y; s.z += bv.z; s.w += bv.w;

    const int n = c4*4;
    const int which = n >> 11, e = n & 2047, h = e >> 7, d = e & 127;
    const int b = m >> 3, t = m & 7;
    if (which == 0) {
        s.x *= SCALE_; s.y *= SCALE_; s.z *= SCALE_; s.w *= SCALE_;
        ((float4*)d_q)[((b*H_ + h)*T_ + t)*32 + (d >> 2)] = s;
    } else if (which == 1) {
        ((float4*)out)[OFF_K4 + ((size_t)((b*H_ + h)*ST_ + S_ + t))*32 + (d >> 2)] = s;
    } else {
        ((float4*)out)[OFF_V4 + ((size_t)((b*H_ + h)*ST_ + S_ + t))*32 + (d >> 2)] = s;
    }
}

// ---------------------------------------------------------------------------
// Reduce out-proj partials: sum 8 splits + bias -> out[0 .. 128*2048)
// ---------------------------------------------------------------------------
__global__ __launch_bounds__(256) void reduce_out(
    const float* __restrict__ bias, float* __restrict__ out)
{
    const int idx = blockIdx.x*256 + threadIdx.x;    // 0..65535
    const float4* p4 = (const float4*)d_p2;
    float4 s = p4[idx];
    #pragma unroll
    for (int sp = 1; sp < SPLITK; sp++) {
        float4 tt = p4[sp*65536 + idx];
        s.x += tt.x; s.y += tt.y; s.z += tt.z; s.w += tt.w;
    }
    const int c4 = idx & 511;
    float4 bv = ((const float4*)bias)[c4];
    s.x += bv.x; s.y += bv.y; s.z += bv.z; s.w += bv.w;
    ((float4*)out)[idx] = s;
}

// ---------------------------------------------------------------------------
// K2 v6 "R7-slim": fused cache copy + split-KV partial attention.
// grid 4096 = (bh=256) x (split=16), 256 threads, 8 tiles of 32 keys.
//  - V never in smem: LDG->regs, PV from regs (warp owns keys 4w..4w+3,
//    per-query packed accumulators), V copy-out STG from regs in PV phase,
//    next-V LDG right after (latency covered by stage+score+softmax).
//  - K: regs -> STS (single 17KB buffer) + copy-out STG from regs; next-K
//    LDG right after barA into the (now dead) kk registers — no extra
//    prefetch registers, no spills.
//  - One static 32KB smem block, aliased: [K tile | q | s/p/a] during the
//    loop, whole block reused for the final cross-warp o-reduction.
//  - __launch_bounds__(256,3): 3 CTAs/SM (reg cap 85 vs ~80 est. usage).
//  - 3 barriers/tile.
// ---------------------------------------------------------------------------
__global__ __launch_bounds__(256, 3) void attn_partial(
    const float* __restrict__ ck, const float* __restrict__ cv,
    float* __restrict__ out)
{
    __shared__ __align__(16) float4 smem[2048];          // 32KB
    float4* kbuf = smem;                                 // [0..1055]  r*33+c
    float4* q4s  = smem + 1056;                          // [0..263]   t*33+c
    float*  fb   = (float*)(smem + 1320);
    float*  s_sh = fb;                                   // [0..263]   t*33+j
    float*  p_sh = fb + 264;
    float*  a_sh = fb + 528;

    const int blk   = blockIdx.x;
    const int bh    = blk >> 4;
    const int split = blk & 15;
    const int tid   = threadIdx.x;
    const int w     = tid >> 5;
    const int lane  = tid & 31;

    const float4* ck4 = (const float4*)ck;
    const float4* cv4 = (const float4*)cv;
    float4* out4 = (float4*)out;

    q4s[w*33 + lane] = ((const float4*)d_q)[(size_t)bh*256 + w*32 + lane];

    const int s_base = split * KPS;
    const int sj = 4*w + (lane & 3);      // score: owned key
    const int st = lane >> 2;             // score: owned query

    float m_cur = -1e30f, l_cur = 0.0f;
    ULL o_acc[T_][2];                     // query-t partial over this warp's keys
    #pragma unroll
    for (int t = 0; t < T_; t++) { o_acc[t][0] = 0ULL; o_acc[t][1] = 0ULL; }

    // prefetch tile 0: thread holds rows {4w..4w+3}, f4-chunk lane
    float4 kk[4], vv[4];
    #pragma unroll
    for (int i = 0; i < 4; i++) {
        size_t src = ((size_t)bh*S_ + s_base + 4*w + i)*32 + lane;
        kk[i] = ck4[src]; vv[i] = cv4[src];
    }

    #pragma unroll
    for (int tile = 0; tile < 8; tile++) {
        const int s0 = s_base + tile*32;

        // ---- stage K: STS + copy-out STG straight from registers ----
        #pragma unroll
        for (int i = 0; i < 4; i++) {
            int r = 4*w + i;
            kbuf[r*33 + lane] = kk[i];
            out4[OFF_K4 + ((size_t)bh*ST_ + s0 + r)*32 + lane] = kk[i];
        }
        __syncthreads();   // barA

        // next-tile K into the now-dead kk regs (covered by score+softmax+PV)
        if (tile < 7) {
            #pragma unroll
            for (int i = 0; i < 4; i++)
                kk[i] = ck4[((size_t)bh*S_ + s0 + 32 + 4*w + i)*32 + lane];
        }

        // ---- score: thread (key sj, query st), full 128-dim dot in-thread ----
        {
            ULL acc0 = 0ULL, acc1 = 0ULL;
            #pragma unroll
            for (int c = 0; c < 32; c++) {
                float4 kv = kbuf[sj*33 + c];     // 4 distinct 16B addrs/warp
                float4 qq = q4s[st*33 + c];      // 8 distinct 16B addrs/warp
                ffma2(acc0, pack2(kv.x, kv.y), pack2(qq.x, qq.y));
                ffma2(acc1, pack2(kv.z, kv.w), pack2(qq.z, qq.w));
            }
            float a0x, a0y, a1x, a1y;
            unpack2(acc0, a0x, a0y);
            unpack2(acc1, a1x, a1y);
            s_sh[st*33 + sj] = (a0x + a0y) + (a1x + a1y);
        }
        __syncthreads();   // barB

        // ---- online softmax: warp w = query w, lane = key ----
        {
            float sc = s_sh[w*33 + lane];
            float mt = sc;
            #pragma unroll
            for (int off = 16; off; off >>= 1)
                mt = fmaxf(mt, __shfl_xor_sync(0xffffffffu, mt, off));
            float m_new = fmaxf(m_cur, mt);
            float p = __expf(sc - m_new);
            float ps = p;
            #pragma unroll
            for (int off = 16; off; off >>= 1)
                ps += __shfl_xor_sync(0xffffffffu, ps, off);
            float al = __expf(m_cur - m_new);
            l_cur = l_cur*al + ps;
            m_cur = m_new;
            p_sh[w*33 + lane] = p;
            if (lane == 0) a_sh[w] = al;
        }
        __syncthreads();   // barC

        // ---- PV from V registers (warp's 4 keys, all 8 queries) ----
        #pragma unroll
        for (int t = 0; t < T_; t++) {
            float alv = a_sh[t];                 // warp-uniform
            ULL alp = pack2(alv, alv);
            mul2(o_acc[t][0], o_acc[t][0], alp);
            mul2(o_acc[t][1], o_acc[t][1], alp);
            #pragma unroll
            for (int i = 0; i < 4; i++) {
                float pv = p_sh[t*33 + 4*w + i]; // warp-uniform
                ULL pp = pack2(pv, pv);
                ffma2(o_acc[t][0], pp, pack2(vv[i].x, vv[i].y));
                ffma2(o_acc[t][1], pp, pack2(vv[i].z, vv[i].w));
            }
        }
        // V copy-out from regs, then next-V LDG (covered into next tile)
        #pragma unroll
        for (int i = 0; i < 4; i++)
            out4[OFF_V4 + ((size_t)bh*ST_ + s0 + 4*w + i)*32 + lane] = vv[i];
        if (tile < 7) {
            #pragma unroll
            for (int i = 0; i < 4; i++)
                vv[i] = cv4[((size_t)bh*S_ + s0 + 32 + 4*w + i)*32 + lane];
        }
        // next stage's kbuf STS is fenced from this tile's score reads by
        // barB+barC; p_sh/a_sh rewrite is fenced by next barA+barB.
    }

    // ---- cross-warp o reduction, reusing the whole 32KB block ----
    __syncthreads();
    #pragma unroll
    for (int t = 0; t < T_; t++) {
        float x0, x1, x2, x3;
        unpack2(o_acc[t][0], x0, x1);
        unpack2(o_acc[t][1], x2, x3);
        smem[(w*T_ + t)*32 + lane] = make_float4(x0, x1, x2, x3);
    }
    __syncthreads();
    {
        float4 osum = make_float4(0.f, 0.f, 0.f, 0.f);
        #pragma unroll
        for (int sw = 0; sw < 8; sw++) {
            float4 v = smem[(sw*T_ + w)*32 + lane];
            osum.x += v.x; osum.y += v.y; osum.z += v.z; osum.w += v.w;
        }
        ((float4*)d_part_o)[((size_t)blk*T_ + w)*32 + lane] = osum;
        if (lane == 0) {
            d_part_m[blk*T_ + w] = m_cur;
            d_part_l[blk*T_ + w] = l_cur;
        }
    }
}

// ---------------------------------------------------------------------------
// K3: combine 16 split partials + causal-masked new keys.
// grid 512 x 128: warp handles one (bh,t) task.
// ---------------------------------------------------------------------------
__global__ __launch_bounds__(128) void attn_combine(const float* __restrict__ out_ro)
{
    const int task = blockIdx.x*4 + (threadIdx.x >> 5);   // 0..2047
    const int bh   = task >> 3;
    const int t    = task & 7;
    const int lane = threadIdx.x & 31;

    const float4* q4 = (const float4*)d_q;
    const float4* o4 = (const float4*)out_ro;
    const float4* po4 = (const float4*)d_part_o;

    float4 qv = q4[(size_t)(bh*T_ + t)*32 + lane];

    float sj[T_];
    float m_new = -1e30f;
    #pragma unroll
    for (int j = 0; j < T_; j++) {
        float sc = -1e30f;
        if (j <= t) {
            float4 kv = o4[OFF_K4 + ((size_t)bh*ST_ + S_ + j)*32 + lane];
            float p = qv.x*kv.x + qv.y*kv.y + qv.z*kv.z + qv.w*kv.w;
            #pragma unroll
            for (int off = 16; off; off >>= 1)
                p += __shfl_xor_sync(0xffffffffu, p, off);
            sc = p;
        }
        sj[j] = sc;
        m_new = fmaxf(m_new, sc);
    }

    float pm[NSPLIT], pl[NSPLIT];
    #pragma unroll
    for (int s = 0; s < NSPLIT; s++) {
        pm[s] = d_part_m[(bh*NSPLIT + s)*T_ + t];
        pl[s] = d_part_l[(bh*NSPLIT + s)*T_ + t];
        m_new = fmaxf(m_new, pm[s]);
    }

    float denom = 0.0f;
    float4 acc = make_float4(0.f, 0.f, 0.f, 0.f);
    #pragma unroll
    for (int s = 0; s < NSPLIT; s++) {
        float ws = __expf(pm[s] - m_new);
        denom += ws * pl[s];
        float4 po = po4[((size_t)(bh*NSPLIT + s)*T_ + t)*32 + lane];
        acc.x = fmaf(ws, po.x, acc.x);
        acc.y = fmaf(ws, po.y, acc.y);
        acc.z = fmaf(ws, po.z, acc.z);
        acc.w = fmaf(ws, po.w, acc.w);
    }
    #pragma unroll
    for (int j = 0; j < T_; j++) {
        if (j <= t) {
            float p = __expf(sj[j] - m_new);
            denom += p;
            float4 vv = o4[OFF_V4 + ((size_t)bh*ST_ + S_ + j)*32 + lane];
            acc.x = fmaf(p, vv.x, acc.x);
            acc.y = fmaf(p, vv.y, acc.y);
            acc.z = fmaf(p, vv.z, acc.z);
            acc.w = fmaf(p, vv.w, acc.w);
        }
    }

    float inv = 1.0f / denom;
    acc.x *= inv; acc.y *= inv; acc.z *= inv; acc.w *= inv;

    float4* a4 = (float4*)d_attn;
    int b = bh >> 4, h = bh & 15;
    a4[((size_t)(b*T_ + t))*512 + h*32 + lane] = acc;
}

// ---------------------------------------------------------------------------
extern "C" void kernel_launch(void* const* d_in, const int* in_sizes, int n_in,
                              void* d_out, int out_size)
{
    const float* x      = (const float*)d_in[0];
    const float* ck     = (const float*)d_in[1];
    const float* cv     = (const float*)d_in[2];
    const float* w_qkv  = (const float*)d_in[3];
    const float* b_qkv  = (const float*)d_in[4];
    const float* w_out  = (const float*)d_in[5];
    const float* b_out  = (const float*)d_in[6];
    float* out = (float*)d_out;

    gemm128<<<dim3(48, SPLITK), 256>>>(x, w_qkv, 6144, 2048, 0);      // launch 0
    reduce_qkv<<<384, 256>>>(b_qkv, out, 0);                          // launch 1
    reduce_qkv<<<384, 256>>>(b_qkv, out, 384);                        // launch 2
    attn_partial<<<B_*H_*NSPLIT, 256>>>(ck, cv, out);                 // launch 3 (ncu)
    attn_combine<<<512, 128>>>(out);
    gemm128<<<dim3(16, SPLITK), 256>>>(nullptr, w_out, 2048, 2048, 1);
    reduce_out<<<256, 256>>>(b_out, out);
}